// round 14
// baseline (speedup 1.0000x reference)
#include <cuda_runtime.h>
#include <cuda_fp16.h>
#include <cstdint>

#define NTOK    49
#define NHEADS  16
#define HDIM    32
#define DIMC    512
#define BATCH   2048
#define NWIN    64
#define QK_SCALE 0.17677669529663687f   // 32^-0.5
#define M_TOT   (BATCH * NTOK)          // 100352

// ---------------- scratch (device globals: allocation-free) ----------------
__device__ __half g_qkvh[(size_t)M_TOT * 3 * DIMC];   // (M, 1536) fp16
__device__ __half g_obuf[(size_t)M_TOT * DIMC];       // (M, 512)  fp16
__device__ __half g_xh  [(size_t)M_TOT * DIMC];       // x in fp16
__device__ __half g_wqkv[(size_t)3 * DIMC * DIMC];    // qkv_w fp16
__device__ __half g_wprj[(size_t)DIMC * DIMC];        // proj_w fp16

// ---------------- helpers ---------------------------------------------------
__device__ __forceinline__ uint32_t sptr(const void* p) {
    return (uint32_t)__cvta_generic_to_shared(p);
}
__device__ __forceinline__ void ldsm4(uint32_t* r, uint32_t a) {
    asm volatile("ldmatrix.sync.aligned.m8n8.x4.shared.b16 {%0,%1,%2,%3}, [%4];"
                 : "=r"(r[0]), "=r"(r[1]), "=r"(r[2]), "=r"(r[3]) : "r"(a));
}
__device__ __forceinline__ void ldsm4t(uint32_t* r, uint32_t a) {
    asm volatile("ldmatrix.sync.aligned.m8n8.x4.trans.shared.b16 {%0,%1,%2,%3}, [%4];"
                 : "=r"(r[0]), "=r"(r[1]), "=r"(r[2]), "=r"(r[3]) : "r"(a));
}
__device__ __forceinline__ void mma16816(float* c, const uint32_t* a, const uint32_t* b) {
    asm volatile(
        "mma.sync.aligned.m16n8k16.row.col.f32.f16.f16.f32 "
        "{%0,%1,%2,%3}, {%4,%5,%6,%7}, {%8,%9}, {%0,%1,%2,%3};\n"
        : "+f"(c[0]), "+f"(c[1]), "+f"(c[2]), "+f"(c[3])
        : "r"(a[0]), "r"(a[1]), "r"(a[2]), "r"(a[3]), "r"(b[0]), "r"(b[1]));
}
// fp16-accumulator variant: D/C are 2x f16x2 regs, same logical layout
__device__ __forceinline__ void mma16816h(uint32_t* d, const uint32_t* a, const uint32_t* b) {
    asm volatile(
        "mma.sync.aligned.m16n8k16.row.col.f16.f16.f16.f16 "
        "{%0,%1}, {%2,%3,%4,%5}, {%6,%7}, {%0,%1};\n"
        : "+r"(d[0]), "+r"(d[1])
        : "r"(a[0]), "r"(a[1]), "r"(a[2]), "r"(a[3]), "r"(b[0]), "r"(b[1]));
}
__device__ __forceinline__ uint32_t packh2(float lo, float hi) {
    __half2 h = __floats2half2_rn(lo, hi);
    return *(uint32_t*)&h;
}

// ---------------- fp32 -> fp16 convert (vectorized) ------------------------
__global__ void f2h_kernel(const float* __restrict__ in, __half* __restrict__ out, long n4)
{
    long i = (long)blockIdx.x * blockDim.x + threadIdx.x;
    if (i >= n4) return;
    float4 v = ((const float4*)in)[i];
    uint2 p;
    p.x = packh2(v.x, v.y);
    p.y = packh2(v.z, v.w);
    ((uint2*)out)[i] = p;
}

// ============================================================================
// FP16 GEMM, chunked fp16 accumulation (promote to fp32 every K=64):
// C[M,N] = A[M,512] * B[N,512]^T + bias[N]
// Block tile 128x128, BK=64, 128 threads = 4 warps (2m x 2n), warp tile 64x64.
// 2-stage cp.async, single-buffered ldmatrix fragments. 144B padded rows.
// 2 CTAs/SM.
// ============================================================================

#define BK      64
#define ROWH    72                    // halves per padded row (144 B)
#define BM      128
#define BN      128
#define ASTG    (BM * ROWH)
#define BSTG    (BN * ROWH)
#define NSTAGE  2
#define SMEM_GEMM (NSTAGE * (ASTG + BSTG) * 2)   // 73728 B

template<class OutT>
__global__ __launch_bounds__(128, 2)
void gemm_hf(const __half* __restrict__ A, const __half* __restrict__ B,
             const float* __restrict__ bias, OutT* __restrict__ C, int N)
{
    extern __shared__ __half sm[];
    __half* As = sm;                          // NSTAGE * ASTG
    __half* Bs = sm + NSTAGE * ASTG;          // NSTAGE * BSTG

    const int tid  = threadIdx.x;
    const int warp = tid >> 5, lane = tid & 31;
    const int wm   = warp >> 1, wn = warp & 1;     // warp tile (wm*64, wn*64)
    const int grp  = lane >> 2, tig = lane & 3;

    const long rowM0 = (long)blockIdx.y * BM;
    const long rowN0 = (long)blockIdx.x * BN;

    float acc[4][8][4];                // fp32 running sums
    #pragma unroll
    for (int i = 0; i < 4; i++)
        #pragma unroll
        for (int j = 0; j < 8; j++)
            #pragma unroll
            for (int q = 0; q < 4; q++) acc[i][j][q] = 0.f;

    uint32_t hacc[4][8][2];            // fp16 chunk accumulators

    // stage fill: A and B each 128 rows x 128B = 1024 x 16B chunks; 8/thread
    auto issue = [&](int s, int kt) {
        const __half* ga = A + rowM0 * DIMC + kt * BK;
        const __half* gb = B + rowN0 * DIMC + kt * BK;
        __half* sa = As + s * ASTG;
        __half* sb = Bs + s * BSTG;
        #pragma unroll
        for (int i = 0; i < 8; i++) {
            int q = tid + 128 * i;
            int r = q >> 3, c = (q & 7) * 8;      // row 0..127, half-col 0..56
            asm volatile("cp.async.cg.shared.global [%0], [%1], 16;\n"
                         :: "r"(sptr(sa + r * ROWH + c)), "l"(ga + (long)r * DIMC + c));
            asm volatile("cp.async.cg.shared.global [%0], [%1], 16;\n"
                         :: "r"(sptr(sb + r * ROWH + c)), "l"(gb + (long)r * DIMC + c));
        }
        asm volatile("cp.async.commit_group;\n");
    };

    const int NK = DIMC / BK;   // 8
    issue(0, 0);

    const int aRow = ((lane >> 3) & 1) * 8 + (lane & 7);
    const int aCol = ((lane >> 4) & 1) * 8;
    const int bRow = ((lane >> 4) & 1) * 8 + (lane & 7);
    const int bCol = ((lane >> 3) & 1) * 8;

    for (int kt = 0; kt < NK; kt++) {
        const int s = kt & 1;
        asm volatile("cp.async.wait_group 0;\n");
        __syncthreads();
        if (kt + 1 < NK) issue(s ^ 1, kt + 1);

        const __half* sa = As + s * ASTG + (wm * 64) * ROWH;
        const __half* sb = Bs + s * BSTG + (wn * 64) * ROWH;

        // zero fp16 chunk accumulators
        #pragma unroll
        for (int mi = 0; mi < 4; mi++)
            #pragma unroll
            for (int ni = 0; ni < 8; ni++) { hacc[mi][ni][0] = 0u; hacc[mi][ni][1] = 0u; }

        #pragma unroll
        for (int kk = 0; kk < 4; kk++) {           // 4 x k16 = K=64 chunk
            const int kc = kk * 16;
            uint32_t afr[4][4], bfr[4][4];
            #pragma unroll
            for (int mi = 0; mi < 4; mi++)
                ldsm4(afr[mi], sptr(sa + (mi * 16 + aRow) * ROWH + kc + aCol));
            #pragma unroll
            for (int u = 0; u < 4; u++)
                ldsm4(bfr[u], sptr(sb + (u * 16 + bRow) * ROWH + kc + bCol));
            #pragma unroll
            for (int u = 0; u < 4; u++)
                #pragma unroll
                for (int mi = 0; mi < 4; mi++) {
                    mma16816h(hacc[mi][2 * u],     afr[mi], bfr[u]);
                    mma16816h(hacc[mi][2 * u + 1], afr[mi], bfr[u] + 2);
                }
        }

        // promote chunk to fp32 running sums
        #pragma unroll
        for (int mi = 0; mi < 4; mi++)
            #pragma unroll
            for (int ni = 0; ni < 8; ni++) {
                float2 f0 = __half22float2(*(__half2*)&hacc[mi][ni][0]);
                float2 f1 = __half22float2(*(__half2*)&hacc[mi][ni][1]);
                acc[mi][ni][0] += f0.x;
                acc[mi][ni][1] += f0.y;
                acc[mi][ni][2] += f1.x;
                acc[mi][ni][3] += f1.y;
            }
    }

    // epilogue
    #pragma unroll
    for (int mi = 0; mi < 4; mi++) {
        long r0 = rowM0 + wm * 64 + mi * 16 + grp;
        #pragma unroll
        for (int ni = 0; ni < 8; ni++) {
            long c = rowN0 + wn * 64 + ni * 8 + tig * 2;
            float b0 = bias[c], b1 = bias[c + 1];
            float v00 = acc[mi][ni][0] + b0, v01 = acc[mi][ni][1] + b1;
            float v10 = acc[mi][ni][2] + b0, v11 = acc[mi][ni][3] + b1;
            if constexpr (sizeof(OutT) == 2) {
                *(uint32_t*)((__half*)C + r0 * N + c)       = packh2(v00, v01);
                *(uint32_t*)((__half*)C + (r0 + 8) * N + c) = packh2(v10, v11);
            } else {
                *(float2*)((float*)C + r0 * N + c)       = make_float2(v00, v01);
                *(float2*)((float*)C + (r0 + 8) * N + c) = make_float2(v10, v11);
            }
        }
    }
}

// ============================================================================
// tensor-core window attention: one block = (b, 2 heads), 256 threads.
// ============================================================================
#define AROWH 40

__global__ __launch_bounds__(256)
void attn_mma(const __half* __restrict__ qkv, const float* __restrict__ mask,
              const float* __restrict__ rpb, __half* __restrict__ obuf)
{
    __shared__ __half qs[2][64 * AROWH], ks[2][64 * AROWH], vs[2][64 * AROWH];
    __shared__ float masks[NTOK * NTOK];
    __shared__ float rpbs[2][169];

    const int b   = blockIdx.y;
    const int h   = blockIdx.x * 2 + (threadIdx.x >> 7);
    const int hi  = threadIdx.x >> 7;
    const int t128 = threadIdx.x & 127;
    const int wid = t128 >> 5, lane = threadIdx.x & 31;
    const int grp = lane >> 2, tig = lane & 3;

    // zero tiles
    for (int i = t128; i < 64 * AROWH / 2; i += 128) {
        ((uint32_t*)qs[hi])[i] = 0; ((uint32_t*)ks[hi])[i] = 0; ((uint32_t*)vs[hi])[i] = 0;
    }
    __syncthreads();

    // fill q/k/v rows (half2 copies) + mask + rpb
    {
        const __half* base = qkv + (long)(b * NTOK) * (3 * DIMC) + h * HDIM;
        for (int idx = t128; idx < NTOK * 16; idx += 128) {
            int n = idx >> 4, d2 = (idx & 15) * 2;
            const __half* p = base + (long)n * (3 * DIMC) + d2;
            *(uint32_t*)(qs[hi] + n * AROWH + d2) = *(const uint32_t*)(p);
            *(uint32_t*)(ks[hi] + n * AROWH + d2) = *(const uint32_t*)(p + DIMC);
            *(uint32_t*)(vs[hi] + n * AROWH + d2) = *(const uint32_t*)(p + 2 * DIMC);
        }
        const int w = b & (NWIN - 1);
        const float* mp = mask + (long)w * NTOK * NTOK;
        for (int i = threadIdx.x; i < NTOK * NTOK; i += 256) masks[i] = mp[i];
        for (int i = t128; i < 169; i += 128) rpbs[hi][i] = rpb[i * NHEADS + h];
    }
    __syncthreads();

    // ---- S = Q K^T ----
    const int aRow = wid * 16 + ((lane >> 3) & 1) * 8 + (lane & 7);
    const int aCol = ((lane >> 4) & 1) * 8;
    const int bRow = ((lane >> 4) & 1) * 8 + (lane & 7);
    const int bCol = ((lane >> 3) & 1) * 8;

    float sacc[7][4];
    #pragma unroll
    for (int t = 0; t < 7; t++)
        #pragma unroll
        for (int e = 0; e < 4; e++) sacc[t][e] = 0.f;

    #pragma unroll
    for (int kk = 0; kk < 2; kk++) {
        const int kc = kk * 16;
        uint32_t a[4];
        ldsm4(a, sptr(qs[hi] + aRow * AROWH + kc + aCol));
        #pragma unroll
        for (int u = 0; u < 4; u++) {
            uint32_t t4[4];
            ldsm4(t4, sptr(ks[hi] + (u * 16 + bRow) * AROWH + kc + bCol));
            mma16816(sacc[2 * u], a, t4);
            if (2 * u + 1 < 7) mma16816(sacc[2 * u + 1], a, t4 + 2);
        }
    }

    // ---- scale + bias + mask, softmax ----
    const int i0 = wid * 16 + grp;
    const int i1 = i0 + 8;
    const int ih0 = i0 / 7, iw0 = i0 - ih0 * 7;
    const int ih1 = i1 / 7, iw1 = i1 - ih1 * 7;

    #pragma unroll
    for (int t = 0; t < 7; t++) {
        #pragma unroll
        for (int e = 0; e < 4; e++) {
            int c = 8 * t + 2 * tig + (e & 1);
            int i = (e < 2) ? i0 : i1;
            float v = sacc[t][e] * QK_SCALE;
            if (c >= NTOK) v = -1e30f;
            else if (i < NTOK) {
                int ch = c / 7, cw = c - ch * 7;
                int ihh = (e < 2) ? ih0 : ih1, iww = (e < 2) ? iw0 : iw1;
                int ridx = (ihh - ch + 6) * 13 + (iww - cw + 6);
                v += rpbs[hi][ridx] + masks[i * NTOK + c];
            }
            sacc[t][e] = v;
        }
    }

    float m0 = -1e30f, m1 = -1e30f;
    #pragma unroll
    for (int t = 0; t < 7; t++) {
        m0 = fmaxf(m0, fmaxf(sacc[t][0], sacc[t][1]));
        m1 = fmaxf(m1, fmaxf(sacc[t][2], sacc[t][3]));
    }
    m0 = fmaxf(m0, __shfl_xor_sync(0xffffffffu, m0, 1));
    m0 = fmaxf(m0, __shfl_xor_sync(0xffffffffu, m0, 2));
    m1 = fmaxf(m1, __shfl_xor_sync(0xffffffffu, m1, 1));
    m1 = fmaxf(m1, __shfl_xor_sync(0xffffffffu, m1, 2));

    float s0 = 0.f, s1 = 0.f;
    #pragma unroll
    for (int t = 0; t < 7; t++) {
        sacc[t][0] = __expf(sacc[t][0] - m0); s0 += sacc[t][0];
        sacc[t][1] = __expf(sacc[t][1] - m0); s0 += sacc[t][1];
        sacc[t][2] = __expf(sacc[t][2] - m1); s1 += sacc[t][2];
        sacc[t][3] = __expf(sacc[t][3] - m1); s1 += sacc[t][3];
    }
    s0 += __shfl_xor_sync(0xffffffffu, s0, 1);
    s0 += __shfl_xor_sync(0xffffffffu, s0, 2);
    s1 += __shfl_xor_sync(0xffffffffu, s1, 1);
    s1 += __shfl_xor_sync(0xffffffffu, s1, 2);
    const float inv0 = 1.f / s0, inv1 = 1.f / s1;

    // ---- pack P, O = P V ----
    uint32_t pa[4][4];
    #pragma unroll
    for (int g = 0; g < 4; g++) {
        int t0 = 2 * g, t1 = 2 * g + 1;
        pa[g][0] = packh2(sacc[t0][0], sacc[t0][1]);
        pa[g][1] = packh2(sacc[t0][2], sacc[t0][3]);
        if (t1 < 7) {
            pa[g][2] = packh2(sacc[t1][0], sacc[t1][1]);
            pa[g][3] = packh2(sacc[t1][2], sacc[t1][3]);
        } else { pa[g][2] = 0; pa[g][3] = 0; }
    }

    float oacc[4][4];
    #pragma unroll
    for (int t = 0; t < 4; t++)
        #pragma unroll
        for (int e = 0; e < 4; e++) oacc[t][e] = 0.f;

    const int vRow = ((lane >> 3) & 1) * 8 + (lane & 7);
    const int vCol = ((lane >> 4) & 1) * 8;
    #pragma unroll
    for (int g = 0; g < 4; g++) {
        uint32_t v0[4], v1[4];
        ldsm4t(v0, sptr(vs[hi] + (g * 16 + vRow) * AROWH + 0  + vCol));
        ldsm4t(v1, sptr(vs[hi] + (g * 16 + vRow) * AROWH + 16 + vCol));
        mma16816(oacc[0], pa[g], v0);
        mma16816(oacc[1], pa[g], v0 + 2);
        mma16816(oacc[2], pa[g], v1);
        mma16816(oacc[3], pa[g], v1 + 2);
    }

    const long ob = (long)(b * NTOK) * DIMC + h * HDIM;
    #pragma unroll
    for (int t = 0; t < 4; t++) {
        int c = 8 * t + 2 * tig;
        if (i0 < NTOK)
            *(uint32_t*)(obuf + ob + (long)i0 * DIMC + c) =
                packh2(oacc[t][0] * inv0, oacc[t][1] * inv0);
        if (i1 < NTOK)
            *(uint32_t*)(obuf + ob + (long)i1 * DIMC + c) =
                packh2(oacc[t][2] * inv1, oacc[t][3] * inv1);
    }
}

// ---------------- launch (serial, R11 structure) ---------------------------
extern "C" void kernel_launch(void* const* d_in, const int* in_sizes, int n_in,
                              void* d_out, int out_size)
{
    const float* x      = (const float*)d_in[0];
    const float* mask   = (const float*)d_in[1];
    const float* qkv_w  = (const float*)d_in[2];
    const float* qkv_b  = (const float*)d_in[3];
    const float* proj_w = (const float*)d_in[4];
    const float* proj_b = (const float*)d_in[5];
    const float* rpb    = (const float*)d_in[6];
    float* out = (float*)d_out;

    __half *qkvh = nullptr, *obuf = nullptr, *xh = nullptr, *wqkv = nullptr, *wprj = nullptr;
    cudaGetSymbolAddress((void**)&qkvh, g_qkvh);
    cudaGetSymbolAddress((void**)&obuf, g_obuf);
    cudaGetSymbolAddress((void**)&xh,   g_xh);
    cudaGetSymbolAddress((void**)&wqkv, g_wqkv);
    cudaGetSymbolAddress((void**)&wprj, g_wprj);

    cudaFuncSetAttribute(gemm_hf<__half>, cudaFuncAttributeMaxDynamicSharedMemorySize, SMEM_GEMM);
    cudaFuncSetAttribute(gemm_hf<float>,  cudaFuncAttributeMaxDynamicSharedMemorySize, SMEM_GEMM);

    // 0) fp32 -> fp16 converts
    {
        long n4 = (long)M_TOT * DIMC / 4;
        f2h_kernel<<<(unsigned)((n4 + 255) / 256), 256>>>(x, xh, n4);
        long w4 = (long)3 * DIMC * DIMC / 4;
        f2h_kernel<<<(unsigned)((w4 + 255) / 256), 256>>>(qkv_w, wqkv, w4);
        long p4 = (long)DIMC * DIMC / 4;
        f2h_kernel<<<(unsigned)((p4 + 255) / 256), 256>>>(proj_w, wprj, p4);
    }

    // 1) qkv = x @ qkv_w^T + qkv_b   -> fp16 (M x 1536)
    dim3 g1(3 * DIMC / BN, M_TOT / BM);
    gemm_hf<__half><<<g1, 128, SMEM_GEMM>>>(xh, wqkv, qkv_b, qkvh, 3 * DIMC);

    // 2) tensor-core windowed attention -> fp16 (M x 512)
    attn_mma<<<dim3(NHEADS / 2, BATCH), 256>>>(qkvh, mask, rpb, obuf);

    // 3) out = attn_out @ proj_w^T + proj_b   (M x 512) fp32
    dim3 g2(DIMC / BN, M_TOT / BM);
    gemm_hf<float><<<g2, 128, SMEM_GEMM>>>(obuf, wprj, proj_b, out, DIMC);
}

// round 15
// speedup vs baseline: 1.2076x; 1.2076x over previous
#include <cuda_runtime.h>
#include <cuda_fp16.h>
#include <cstdint>

#define NTOK    49
#define NHEADS  16
#define HDIM    32
#define DIMC    512
#define BATCH   2048
#define NWIN    64
#define QK_SCALE 0.17677669529663687f   // 32^-0.5
#define M_TOT   (BATCH * NTOK)          // 100352

// ---------------- scratch (device globals: allocation-free) ----------------
__device__ __half g_qkvh[(size_t)M_TOT * 3 * DIMC];   // (M, 1536) fp16
__device__ __half g_obuf[(size_t)M_TOT * DIMC];       // (M, 512)  fp16
__device__ __half g_xh  [(size_t)M_TOT * DIMC];       // x in fp16
__device__ __half g_wqkv[(size_t)3 * DIMC * DIMC];    // qkv_w fp16
__device__ __half g_wprj[(size_t)DIMC * DIMC];        // proj_w fp16

// ---------------- helpers ---------------------------------------------------
__device__ __forceinline__ uint32_t sptr(const void* p) {
    return (uint32_t)__cvta_generic_to_shared(p);
}
__device__ __forceinline__ void ldsm4(uint32_t* r, uint32_t a) {
    asm volatile("ldmatrix.sync.aligned.m8n8.x4.shared.b16 {%0,%1,%2,%3}, [%4];"
                 : "=r"(r[0]), "=r"(r[1]), "=r"(r[2]), "=r"(r[3]) : "r"(a));
}
__device__ __forceinline__ void ldsm4t(uint32_t* r, uint32_t a) {
    asm volatile("ldmatrix.sync.aligned.m8n8.x4.trans.shared.b16 {%0,%1,%2,%3}, [%4];"
                 : "=r"(r[0]), "=r"(r[1]), "=r"(r[2]), "=r"(r[3]) : "r"(a));
}
__device__ __forceinline__ void mma16816(float* c, const uint32_t* a, const uint32_t* b) {
    asm volatile(
        "mma.sync.aligned.m16n8k16.row.col.f32.f16.f16.f32 "
        "{%0,%1,%2,%3}, {%4,%5,%6,%7}, {%8,%9}, {%0,%1,%2,%3};\n"
        : "+f"(c[0]), "+f"(c[1]), "+f"(c[2]), "+f"(c[3])
        : "r"(a[0]), "r"(a[1]), "r"(a[2]), "r"(a[3]), "r"(b[0]), "r"(b[1]));
}
__device__ __forceinline__ uint32_t packh2(float lo, float hi) {
    __half2 h = __floats2half2_rn(lo, hi);
    return *(uint32_t*)&h;
}
__device__ __forceinline__ void cpa16(uint32_t dst, const void* src) {
    asm volatile("cp.async.cg.shared.global [%0], [%1], 16;\n" :: "r"(dst), "l"(src));
}
__device__ __forceinline__ void cpa4(uint32_t dst, const void* src) {
    asm volatile("cp.async.ca.shared.global [%0], [%1], 4;\n" :: "r"(dst), "l"(src));
}

// ---------------- fp32 -> fp16 convert (vectorized) ------------------------
__global__ void f2h_kernel(const float* __restrict__ in, __half* __restrict__ out, long n4)
{
    long i = (long)blockIdx.x * blockDim.x + threadIdx.x;
    if (i >= n4) return;
    float4 v = ((const float4*)in)[i];
    uint2 p;
    p.x = packh2(v.x, v.y);
    p.y = packh2(v.z, v.w);
    ((uint2*)out)[i] = p;
}

// ============================================================================
// FP16 GEMM (fp32 accum): C[M,N] = A[M,512] * B[N,512]^T + bias[N]
// Block tile 128x128, BK=64, 128 threads = 4 warps (2m x 2n), warp tile 64x64.
// 2-stage cp.async, ldmatrix fragment double-buffer. 144B padded rows.
// (R11 configuration — measured best: gemm1 548us, gemm2 186us.)
// ============================================================================

#define BK      64
#define ROWH    72                    // halves per padded row (144 B)
#define BM      128
#define BN      128
#define ASTG    (BM * ROWH)
#define BSTG    (BN * ROWH)
#define NSTAGE  2
#define SMEM_GEMM (NSTAGE * (ASTG + BSTG) * 2)   // 73728 B

template<class OutT>
__global__ __launch_bounds__(128, 2)
void gemm_hf(const __half* __restrict__ A, const __half* __restrict__ B,
             const float* __restrict__ bias, OutT* __restrict__ C, int N)
{
    extern __shared__ __half sm[];
    __half* As = sm;                          // NSTAGE * ASTG
    __half* Bs = sm + NSTAGE * ASTG;          // NSTAGE * BSTG

    const int tid  = threadIdx.x;
    const int warp = tid >> 5, lane = tid & 31;
    const int wm   = warp >> 1, wn = warp & 1;     // warp tile (wm*64, wn*64)
    const int grp  = lane >> 2, tig = lane & 3;

    const long rowM0 = (long)blockIdx.y * BM;
    const long rowN0 = (long)blockIdx.x * BN;

    float acc[4][8][4];
    #pragma unroll
    for (int i = 0; i < 4; i++)
        #pragma unroll
        for (int j = 0; j < 8; j++)
            #pragma unroll
            for (int q = 0; q < 4; q++) acc[i][j][q] = 0.f;

    auto issue = [&](int s, int kt) {
        const __half* ga = A + rowM0 * DIMC + kt * BK;
        const __half* gb = B + rowN0 * DIMC + kt * BK;
        __half* sa = As + s * ASTG;
        __half* sb = Bs + s * BSTG;
        #pragma unroll
        for (int i = 0; i < 8; i++) {
            int q = tid + 128 * i;
            int r = q >> 3, c = (q & 7) * 8;
            cpa16(sptr(sa + r * ROWH + c), ga + (long)r * DIMC + c);
            cpa16(sptr(sb + r * ROWH + c), gb + (long)r * DIMC + c);
        }
        asm volatile("cp.async.commit_group;\n");
    };

    const int NK = DIMC / BK;   // 8
    issue(0, 0);

    const int aRow = ((lane >> 3) & 1) * 8 + (lane & 7);
    const int aCol = ((lane >> 4) & 1) * 8;
    const int bRow = ((lane >> 4) & 1) * 8 + (lane & 7);
    const int bCol = ((lane >> 3) & 1) * 8;

    uint32_t afr[2][4][4], bfr[2][4][4];

    for (int kt = 0; kt < NK; kt++) {
        const int s = kt & 1;
        asm volatile("cp.async.wait_group 0;\n");
        __syncthreads();
        if (kt + 1 < NK) issue(s ^ 1, kt + 1);

        const __half* sa = As + s * ASTG + (wm * 64) * ROWH;
        const __half* sb = Bs + s * BSTG + (wn * 64) * ROWH;

        #pragma unroll
        for (int mi = 0; mi < 4; mi++)
            ldsm4(afr[0][mi], sptr(sa + (mi * 16 + aRow) * ROWH + aCol));
        #pragma unroll
        for (int u = 0; u < 4; u++)
            ldsm4(bfr[0][u], sptr(sb + (u * 16 + bRow) * ROWH + bCol));

        #pragma unroll
        for (int kk = 0; kk < 4; kk++) {           // 4 x k16
            const int cur = kk & 1;
            if (kk + 1 < 4) {
                const int kc = (kk + 1) * 16;
                #pragma unroll
                for (int mi = 0; mi < 4; mi++)
                    ldsm4(afr[cur ^ 1][mi], sptr(sa + (mi * 16 + aRow) * ROWH + kc + aCol));
                #pragma unroll
                for (int u = 0; u < 4; u++)
                    ldsm4(bfr[cur ^ 1][u], sptr(sb + (u * 16 + bRow) * ROWH + kc + bCol));
            }
            #pragma unroll
            for (int u = 0; u < 4; u++)
                #pragma unroll
                for (int mi = 0; mi < 4; mi++) {
                    mma16816(acc[mi][2 * u],     afr[cur][mi], bfr[cur][u]);
                    mma16816(acc[mi][2 * u + 1], afr[cur][mi], bfr[cur][u] + 2);
                }
        }
    }

    // epilogue
    #pragma unroll
    for (int mi = 0; mi < 4; mi++) {
        long r0 = rowM0 + wm * 64 + mi * 16 + grp;
        #pragma unroll
        for (int ni = 0; ni < 8; ni++) {
            long c = rowN0 + wn * 64 + ni * 8 + tig * 2;
            float b0 = bias[c], b1 = bias[c + 1];
            float v00 = acc[mi][ni][0] + b0, v01 = acc[mi][ni][1] + b1;
            float v10 = acc[mi][ni][2] + b0, v11 = acc[mi][ni][3] + b1;
            if constexpr (sizeof(OutT) == 2) {
                *(uint32_t*)((__half*)C + r0 * N + c)       = packh2(v00, v01);
                *(uint32_t*)((__half*)C + (r0 + 8) * N + c) = packh2(v10, v11);
            } else {
                *(float2*)((float*)C + r0 * N + c)       = make_float2(v00, v01);
                *(float2*)((float*)C + (r0 + 8) * N + c) = make_float2(v10, v11);
            }
        }
    }
}

// ============================================================================
// tensor-core window attention: one block = (b, 2 heads), 256 threads.
// cp.async fill (qkv 16B chunks, mask/rpb 4B); zero only vs rows 49-63
// (pad cols never read by ldmatrix; qs/ks garbage rows provably masked).
// ============================================================================
#define AROWH 40

__global__ __launch_bounds__(256)
void attn_mma(const __half* __restrict__ qkv, const float* __restrict__ mask,
              const float* __restrict__ rpb, __half* __restrict__ obuf)
{
    __shared__ __align__(16) __half qs[2][64 * AROWH];
    __shared__ __align__(16) __half ks[2][64 * AROWH];
    __shared__ __align__(16) __half vs[2][64 * AROWH];
    __shared__ __align__(16) float masks[NTOK * NTOK];
    __shared__ __align__(16) float rpbs[2][169];

    const int b   = blockIdx.y;
    const int h   = blockIdx.x * 2 + (threadIdx.x >> 7);
    const int hi  = threadIdx.x >> 7;
    const int t128 = threadIdx.x & 127;
    const int wid = t128 >> 5, lane = threadIdx.x & 31;
    const int grp = lane >> 2, tig = lane & 3;

    // zero ONLY vs rows 49..63, cols 0..31 (multiplied by exact-0 P, must be finite)
    for (int i = t128; i < 15 * 16; i += 128) {
        int r = 49 + (i >> 4), w = i & 15;
        *(uint32_t*)(vs[hi] + r * AROWH + w * 2) = 0u;
    }

    // async fill q/k/v: 49 rows x 4 x 16B chunks per tensor
    {
        const __half* base = qkv + (long)(b * NTOK) * (3 * DIMC) + h * HDIM;
        for (int idx = t128; idx < NTOK * 4; idx += 128) {
            int n = idx >> 2, ck = (idx & 3) * 8;       // half offset 0,8,16,24
            const __half* p = base + (long)n * (3 * DIMC) + ck;
            cpa16(sptr(qs[hi] + n * AROWH + ck), p);
            cpa16(sptr(ks[hi] + n * AROWH + ck), p + DIMC);
            cpa16(sptr(vs[hi] + n * AROWH + ck), p + 2 * DIMC);
        }
        // mask (shared by both heads) + per-head rpb, 4B async
        const int w = b & (NWIN - 1);
        const float* mp = mask + (long)w * NTOK * NTOK;
        for (int i = threadIdx.x; i < NTOK * NTOK; i += 256)
            cpa4(sptr(masks + i), mp + i);
        for (int i = t128; i < 169; i += 128)
            cpa4(sptr(&rpbs[hi][i]), rpb + i * NHEADS + h);
        asm volatile("cp.async.commit_group;\n");
    }
    asm volatile("cp.async.wait_group 0;\n");
    __syncthreads();

    // ---- S = Q K^T ----
    const int aRow = wid * 16 + ((lane >> 3) & 1) * 8 + (lane & 7);
    const int aCol = ((lane >> 4) & 1) * 8;
    const int bRow = ((lane >> 4) & 1) * 8 + (lane & 7);
    const int bCol = ((lane >> 3) & 1) * 8;

    float sacc[7][4];
    #pragma unroll
    for (int t = 0; t < 7; t++)
        #pragma unroll
        for (int e = 0; e < 4; e++) sacc[t][e] = 0.f;

    #pragma unroll
    for (int kk = 0; kk < 2; kk++) {
        const int kc = kk * 16;
        uint32_t a[4];
        ldsm4(a, sptr(qs[hi] + aRow * AROWH + kc + aCol));
        #pragma unroll
        for (int u = 0; u < 4; u++) {
            uint32_t t4[4];
            ldsm4(t4, sptr(ks[hi] + (u * 16 + bRow) * AROWH + kc + bCol));
            mma16816(sacc[2 * u], a, t4);
            if (2 * u + 1 < 7) mma16816(sacc[2 * u + 1], a, t4 + 2);
        }
    }

    // ---- scale + bias + mask, softmax ----
    const int i0 = wid * 16 + grp;
    const int i1 = i0 + 8;
    const int ih0 = i0 / 7, iw0 = i0 - ih0 * 7;
    const int ih1 = i1 / 7, iw1 = i1 - ih1 * 7;

    #pragma unroll
    for (int t = 0; t < 7; t++) {
        #pragma unroll
        for (int e = 0; e < 4; e++) {
            int c = 8 * t + 2 * tig + (e & 1);
            int i = (e < 2) ? i0 : i1;
            float v = sacc[t][e] * QK_SCALE;
            if (c >= NTOK) v = -1e30f;
            else if (i < NTOK) {
                int ch = c / 7, cw = c - ch * 7;
                int ihh = (e < 2) ? ih0 : ih1, iww = (e < 2) ? iw0 : iw1;
                int ridx = (ihh - ch + 6) * 13 + (iww - cw + 6);
                v += rpbs[hi][ridx] + masks[i * NTOK + c];
            }
            sacc[t][e] = v;
        }
    }

    float m0 = -1e30f, m1 = -1e30f;
    #pragma unroll
    for (int t = 0; t < 7; t++) {
        m0 = fmaxf(m0, fmaxf(sacc[t][0], sacc[t][1]));
        m1 = fmaxf(m1, fmaxf(sacc[t][2], sacc[t][3]));
    }
    m0 = fmaxf(m0, __shfl_xor_sync(0xffffffffu, m0, 1));
    m0 = fmaxf(m0, __shfl_xor_sync(0xffffffffu, m0, 2));
    m1 = fmaxf(m1, __shfl_xor_sync(0xffffffffu, m1, 1));
    m1 = fmaxf(m1, __shfl_xor_sync(0xffffffffu, m1, 2));

    float s0 = 0.f, s1 = 0.f;
    #pragma unroll
    for (int t = 0; t < 7; t++) {
        sacc[t][0] = __expf(sacc[t][0] - m0); s0 += sacc[t][0];
        sacc[t][1] = __expf(sacc[t][1] - m0); s0 += sacc[t][1];
        sacc[t][2] = __expf(sacc[t][2] - m1); s1 += sacc[t][2];
        sacc[t][3] = __expf(sacc[t][3] - m1); s1 += sacc[t][3];
    }
    s0 += __shfl_xor_sync(0xffffffffu, s0, 1);
    s0 += __shfl_xor_sync(0xffffffffu, s0, 2);
    s1 += __shfl_xor_sync(0xffffffffu, s1, 1);
    s1 += __shfl_xor_sync(0xffffffffu, s1, 2);
    const float inv0 = 1.f / s0, inv1 = 1.f / s1;

    // ---- pack P, O = P V ----
    uint32_t pa[4][4];
    #pragma unroll
    for (int g = 0; g < 4; g++) {
        int t0 = 2 * g, t1 = 2 * g + 1;
        pa[g][0] = packh2(sacc[t0][0], sacc[t0][1]);
        pa[g][1] = packh2(sacc[t0][2], sacc[t0][3]);
        if (t1 < 7) {
            pa[g][2] = packh2(sacc[t1][0], sacc[t1][1]);
            pa[g][3] = packh2(sacc[t1][2], sacc[t1][3]);
        } else { pa[g][2] = 0; pa[g][3] = 0; }
    }

    float oacc[4][4];
    #pragma unroll
    for (int t = 0; t < 4; t++)
        #pragma unroll
        for (int e = 0; e < 4; e++) oacc[t][e] = 0.f;

    const int vRow = ((lane >> 3) & 1) * 8 + (lane & 7);
    const int vCol = ((lane >> 4) & 1) * 8;
    #pragma unroll
    for (int g = 0; g < 4; g++) {
        uint32_t v0[4], v1[4];
        ldsm4t(v0, sptr(vs[hi] + (g * 16 + vRow) * AROWH + 0  + vCol));
        ldsm4t(v1, sptr(vs[hi] + (g * 16 + vRow) * AROWH + 16 + vCol));
        mma16816(oacc[0], pa[g], v0);
        mma16816(oacc[1], pa[g], v0 + 2);
        mma16816(oacc[2], pa[g], v1);
        mma16816(oacc[3], pa[g], v1 + 2);
    }

    const long ob = (long)(b * NTOK) * DIMC + h * HDIM;
    #pragma unroll
    for (int t = 0; t < 4; t++) {
        int c = 8 * t + 2 * tig;
        if (i0 < NTOK)
            *(uint32_t*)(obuf + ob + (long)i0 * DIMC + c) =
                packh2(oacc[t][0] * inv0, oacc[t][1] * inv0);
        if (i1 < NTOK)
            *(uint32_t*)(obuf + ob + (long)i1 * DIMC + c) =
                packh2(oacc[t][2] * inv1, oacc[t][3] * inv1);
    }
}

// ---------------- launch (serial, R11 structure) ---------------------------
extern "C" void kernel_launch(void* const* d_in, const int* in_sizes, int n_in,
                              void* d_out, int out_size)
{
    const float* x      = (const float*)d_in[0];
    const float* mask   = (const float*)d_in[1];
    const float* qkv_w  = (const float*)d_in[2];
    const float* qkv_b  = (const float*)d_in[3];
    const float* proj_w = (const float*)d_in[4];
    const float* proj_b = (const float*)d_in[5];
    const float* rpb    = (const float*)d_in[6];
    float* out = (float*)d_out;

    __half *qkvh = nullptr, *obuf = nullptr, *xh = nullptr, *wqkv = nullptr, *wprj = nullptr;
    cudaGetSymbolAddress((void**)&qkvh, g_qkvh);
    cudaGetSymbolAddress((void**)&obuf, g_obuf);
    cudaGetSymbolAddress((void**)&xh,   g_xh);
    cudaGetSymbolAddress((void**)&wqkv, g_wqkv);
    cudaGetSymbolAddress((void**)&wprj, g_wprj);

    cudaFuncSetAttribute(gemm_hf<__half>, cudaFuncAttributeMaxDynamicSharedMemorySize, SMEM_GEMM);
    cudaFuncSetAttribute(gemm_hf<float>,  cudaFuncAttributeMaxDynamicSharedMemorySize, SMEM_GEMM);

    // 0) fp32 -> fp16 converts
    {
        long n4 = (long)M_TOT * DIMC / 4;
        f2h_kernel<<<(unsigned)((n4 + 255) / 256), 256>>>(x, xh, n4);
        long w4 = (long)3 * DIMC * DIMC / 4;
        f2h_kernel<<<(unsigned)((w4 + 255) / 256), 256>>>(qkv_w, wqkv, w4);
        long p4 = (long)DIMC * DIMC / 4;
        f2h_kernel<<<(unsigned)((p4 + 255) / 256), 256>>>(proj_w, wprj, p4);
    }

    // 1) qkv = x @ qkv_w^T + qkv_b   -> fp16 (M x 1536)
    dim3 g1(3 * DIMC / BN, M_TOT / BM);
    gemm_hf<__half><<<g1, 128, SMEM_GEMM>>>(xh, wqkv, qkv_b, qkvh, 3 * DIMC);

    // 2) tensor-core windowed attention -> fp16 (M x 512)
    attn_mma<<<dim3(NHEADS / 2, BATCH), 256>>>(qkvh, mask, rpb, obuf);

    // 3) out = attn_out @ proj_w^T + proj_b   (M x 512) fp32
    dim3 g2(DIMC / BN, M_TOT / BM);
    gemm_hf<float><<<g2, 128, SMEM_GEMM>>>(obuf, wprj, proj_b, out, DIMC);
}